// round 14
// baseline (speedup 1.0000x reference)
#include <cuda_runtime.h>
#include <cuda_fp16.h>
#include <cstdint>

// CIN_52553219834054 — per-(batch,d) bilinear 2-layer MLP + pooled FC via fp16 mma.sync.m16n8k16.
// Rows p = (batch_local*64 + d), 128 per CTA (2 batches). N=64 outputs. K=4096 = 64 chunks of 64.
// A[p,i*64+j] = x0[p,i]*h[p,j] synthesized in regs; h-fragments streamed from fragment-major smem
// (HF, lane-stride 12 words -> conflict-free LDS.128) so regs fit occ 3 (launch_bounds 128,3).
// B (W) fragment-major in gmem (prep kernel), streamed with 8 coalesced LDG.128/lane/chunk.

#define THREADS 128

__device__ __align__(16) unsigned g_Wf[524288];   // 2 l x 64 i x 2 nh x 8 j8 x 32 lane x 4 words

__global__ void prep_kernel(const float* __restrict__ W1, const float* __restrict__ W2) {
    unsigned q = blockIdx.x * blockDim.x + threadIdx.x;
    if (q >= 524288u) return;
    unsigned wi   = q & 3u;
    unsigned lane = (q >> 2) & 31u;
    unsigned j8   = (q >> 7) & 7u;
    unsigned nh   = (q >> 10) & 1u;
    unsigned i    = (q >> 11) & 63u;
    unsigned l    = q >> 17;
    unsigned g = lane >> 2, t = lane & 3u;
    unsigned ks = j8 >> 1, qq = j8 & 1u;
    unsigned nt = qq * 2u + (wi >> 1), pair = wi & 1u;
    unsigned o = nh * 32u + nt * 8u + g;
    unsigned jcol = i * 64u + ks * 16u + pair * 8u + 2u * t;
    const float* Wl = l ? W2 : W1;
    __half2 v = __floats2half2_rn(Wl[o * 4096u + jcol], Wl[o * 4096u + jcol + 1u]);
    g_Wf[q] = *(unsigned*)&v;
}

__device__ __forceinline__ void mma16(float& c0, float& c1, float& c2, float& c3,
                                      unsigned a0, unsigned a1, unsigned a2, unsigned a3,
                                      unsigned b0, unsigned b1) {
    asm volatile(
        "mma.sync.aligned.m16n8k16.row.col.f32.f16.f16.f32 "
        "{%0,%1,%2,%3}, {%4,%5,%6,%7}, {%8,%9}, {%0,%1,%2,%3};"
        : "+f"(c0), "+f"(c1), "+f"(c2), "+f"(c3)
        : "r"(a0), "r"(a1), "r"(a2), "r"(a3), "r"(b0), "r"(b1));
}

__global__ __launch_bounds__(THREADS, 3) void CIN_52553219834054_kernel(
    const float* __restrict__ x,
    const float* __restrict__ b1v, const float* __restrict__ b2v,
    const float* __restrict__ Wfc, const float* __restrict__ bfcp,
    float* __restrict__ out)
{
    __shared__ __half    X0p[8192];   // [i64][wm2][g8][k8]               (16 KB)
    __shared__ unsigned  HF[6144];    // [wm2][ks4][kh2][lane*12 + k8]    (24 KB)
    __shared__ float     sb[128];     // b1 | b2
    __shared__ float     swf[128];    // Wfc
    __shared__ float     red[2];

    const int tid  = threadIdx.x;
    const int lane = tid & 31;
    const int wid  = tid >> 5;
    const int g    = lane >> 2;
    const int t    = lane & 3;
    const int wm   = wid >> 1;          // m-half (batch within CTA)
    const int nh   = wid & 1;           // n-half
    const int mb   = wm * 64;
    const int b0g  = blockIdx.x * 2;

    // stage x -> X0p (packed x0 scalars) and HF (fragment-major h0 = x)
    for (int q = tid; q < 2048; q += THREADS) {
        int bl = q >> 10, f = (q >> 4) & 63, d4 = q & 15;
        float4 v = *(const float4*)(x + (size_t)(b0g + bl) * 4096 + f * 64 + d4 * 4);
        int ks = f >> 4, kh = (f >> 3) & 1, tq = (f & 7) >> 1, hs = f & 1;
        float vv[4] = { v.x, v.y, v.z, v.w };
        #pragma unroll
        for (int e = 0; e < 4; e++) {
            int d = d4 * 4 + e;
            __half hv = __float2half(vv[e]);
            X0p[((f * 2 + bl) * 8 + (d & 7)) * 8 + (d >> 3)] = hv;
            int widx = (((bl * 4 + ks) * 2 + kh) * 384) + ((d & 7) * 4 + tq) * 12 + (d >> 3);
            ((__half*)HF)[widx * 2 + hs] = hv;
        }
    }
    if (tid < 64)  { sb[tid] = b1v[tid]; sb[64 + tid] = b2v[tid]; }
    if (tid < 128) swf[tid] = Wfc[tid];
    if (tid < 2)   red[tid] = 0.0f;
    __syncthreads();

    // per-warp B stream base: uint4 index = gc*512 + nh*256 + j8*32 + lane
    const uint4* Wp = (const uint4*)g_Wf + (unsigned)nh * 256u + (unsigned)lane;

    #define LOADB(dst, gc) do { const uint4* _p = Wp + (unsigned)(gc) * 512u; \
        dst[0] = _p[0];   dst[1] = _p[32];  dst[2] = _p[64];  dst[3] = _p[96]; \
        dst[4] = _p[128]; dst[5] = _p[160]; dst[6] = _p[192]; dst[7] = _p[224]; } while (0)

    uint4 bA[8], bB[8];
    LOADB(bA, 0);

    float pool = 0.0f;

    float acc[4][4][4];

    #define CONSUME(buf, ii) do { \
        uint4 xv = *(const uint4*)(X0p + (((ii) * 2 + wm) * 8 + g) * 8); \
        const __half* xh = (const __half*)&xv; \
        __half2 xd[8]; \
        _Pragma("unroll") \
        for (int k8 = 0; k8 < 8; k8++) xd[k8] = __half2half2(xh[k8]); \
        _Pragma("unroll") \
        for (int ks = 0; ks < 4; ks++) { \
            uint4 q0 = buf[ks * 2], q1 = buf[ks * 2 + 1]; \
            const unsigned* hfb = HF + (wm * 4 + ks) * 768 + lane * 12; \
            uint4 ha0 = *(const uint4*)(hfb); \
            uint4 ha1 = *(const uint4*)(hfb + 4); \
            uint4 hb0 = *(const uint4*)(hfb + 384); \
            uint4 hb1 = *(const uint4*)(hfb + 388); \
            unsigned h0[8] = { ha0.x, ha0.y, ha0.z, ha0.w, ha1.x, ha1.y, ha1.z, ha1.w }; \
            unsigned h1[8] = { hb0.x, hb0.y, hb0.z, hb0.w, hb1.x, hb1.y, hb1.z, hb1.w }; \
            _Pragma("unroll") \
            for (int s = 0; s < 4; s++) { \
                __half2 a0h = __hmul2(xd[2 * s],     *(__half2*)&h0[2 * s]); \
                __half2 a1h = __hmul2(xd[2 * s + 1], *(__half2*)&h0[2 * s + 1]); \
                __half2 a2h = __hmul2(xd[2 * s],     *(__half2*)&h1[2 * s]); \
                __half2 a3h = __hmul2(xd[2 * s + 1], *(__half2*)&h1[2 * s + 1]); \
                unsigned a0 = *(unsigned*)&a0h, a1 = *(unsigned*)&a1h; \
                unsigned a2 = *(unsigned*)&a2h, a3 = *(unsigned*)&a3h; \
                mma16(acc[s][0][0], acc[s][0][1], acc[s][0][2], acc[s][0][3], a0, a1, a2, a3, q0.x, q0.y); \
                mma16(acc[s][1][0], acc[s][1][1], acc[s][1][2], acc[s][1][3], a0, a1, a2, a3, q0.z, q0.w); \
                mma16(acc[s][2][0], acc[s][2][1], acc[s][2][2], acc[s][2][3], a0, a1, a2, a3, q1.x, q1.y); \
                mma16(acc[s][3][0], acc[s][3][1], acc[s][3][2], acc[s][3][3], a0, a1, a2, a3, q1.z, q1.w); \
            } \
        } \
    } while (0)

    for (int L = 0; L < 2; L++) {
        #pragma unroll
        for (int s = 0; s < 4; s++)
            #pragma unroll
            for (int nt = 0; nt < 4; nt++)
                #pragma unroll
                for (int k = 0; k < 4; k++) acc[s][nt][k] = 0.0f;

        #pragma unroll 1
        for (int i = 0; i < 64; i += 2) {
            const int gc = L * 64 + i;
            LOADB(bB, gc + 1);
            CONSUME(bA, i);
            if (gc + 2 < 128) LOADB(bA, gc + 2);
            CONSUME(bB, i + 1);
        }

        __syncthreads();   // all warps done reading HF before it is overwritten

        // epilogue: bias + relu, pooled FC, fragment-major writeback for layer 2
        const float* bias = sb + L * 64;
        const float* wf   = swf + L * 64;
        #pragma unroll
        for (int s = 0; s < 4; s++) {
            #pragma unroll
            for (int nt = 0; nt < 4; nt++) {
                int n0 = nh * 32 + nt * 8 + 2 * t;
                int n1 = n0 + 1;
                float h00 = fmaxf(acc[s][nt][0] + bias[n0], 0.0f);
                float h01 = fmaxf(acc[s][nt][1] + bias[n1], 0.0f);
                float h10 = fmaxf(acc[s][nt][2] + bias[n0], 0.0f);
                float h11 = fmaxf(acc[s][nt][3] + bias[n1], 0.0f);
                pool += (h00 + h10) * wf[n0] + (h01 + h11) * wf[n1];
                if (L == 0) {
                    // ks = nh*2 + (nt>>1), kh = nt&1; k8 = 2s (rows r0) / 2s+1 (rows r1)
                    int base = ((wm * 4 + (nh * 2 + (nt >> 1))) * 2 + (nt & 1)) * 384 + lane * 12;
                    __half2 w0 = __floats2half2_rn(h00, h01);
                    __half2 w1 = __floats2half2_rn(h10, h11);
                    HF[base + 2 * s]     = *(unsigned*)&w0;
                    HF[base + 2 * s + 1] = *(unsigned*)&w1;
                }
            }
        }
        __syncthreads();   // publish HF before next layer's fragment loads
    }

    // pooled reduction: warps 0,1 -> batch 0; warps 2,3 -> batch 1
    #pragma unroll
    for (int o = 16; o; o >>= 1) pool += __shfl_xor_sync(0xFFFFFFFFu, pool, o);
    if (lane == 0) atomicAdd(&red[wm], pool);
    __syncthreads();
    if (tid < 2) out[b0g + tid] = red[tid] + bfcp[0];
}

extern "C" void kernel_launch(void* const* d_in, const int* in_sizes, int n_in,
                              void* d_out, int out_size) {
    (void)in_sizes; (void)n_in; (void)out_size;
    const float* x   = (const float*)d_in[0];
    const float* W1  = (const float*)d_in[1];
    const float* b1v = (const float*)d_in[2];
    const float* W2  = (const float*)d_in[3];
    const float* b2v = (const float*)d_in[4];
    const float* Wfc = (const float*)d_in[5];
    const float* bfc = (const float*)d_in[6];
    float* out = (float*)d_out;

    prep_kernel<<<2048, 256>>>(W1, W2);
    CIN_52553219834054_kernel<<<512, THREADS>>>(x, b1v, b2v, Wfc, bfc, out);
}

// round 15
// speedup vs baseline: 1.3253x; 1.3253x over previous
#include <cuda_runtime.h>
#include <cuda_fp16.h>
#include <cstdint>

// CIN_52553219834054 — per-(batch,d) bilinear 2-layer MLP + pooled FC via fp16 mma.sync.m16n8k16.
// 256-thread CTAs, 8 warps tiling m128n64 as 4 m-quarters x 2 n-halves (m32n32 per warp).
// Small live set (acc 32 + hfr 32 + B 32) -> 2 CTAs/SM = 16 warps/SM for latency hiding.
// B (W) fragment-major in gmem (prep), single reg buffer refilled per-ks one chunk ahead.

#define THREADS 256
#define HS_ST 72

__device__ __align__(16) unsigned g_Wf[524288];   // 2 l x 64 i x 2 nh x 8 j8 x 32 lane x 4 words

__global__ void prep_kernel(const float* __restrict__ W1, const float* __restrict__ W2) {
    unsigned q = blockIdx.x * blockDim.x + threadIdx.x;
    if (q >= 524288u) return;
    unsigned wi   = q & 3u;
    unsigned lane = (q >> 2) & 31u;
    unsigned j8   = (q >> 7) & 7u;
    unsigned nh   = (q >> 10) & 1u;
    unsigned i    = (q >> 11) & 63u;
    unsigned l    = q >> 17;
    unsigned g = lane >> 2, t = lane & 3u;
    unsigned ks = j8 >> 1, qq = j8 & 1u;
    unsigned nt = qq * 2u + (wi >> 1), pair = wi & 1u;
    unsigned o = nh * 32u + nt * 8u + g;
    unsigned jcol = i * 64u + ks * 16u + pair * 8u + 2u * t;
    const float* Wl = l ? W2 : W1;
    __half2 v = __floats2half2_rn(Wl[o * 4096u + jcol], Wl[o * 4096u + jcol + 1u]);
    g_Wf[q] = *(unsigned*)&v;
}

__device__ __forceinline__ void mma16(float& c0, float& c1, float& c2, float& c3,
                                      unsigned a0, unsigned a1, unsigned a2, unsigned a3,
                                      unsigned b0, unsigned b1) {
    asm volatile(
        "mma.sync.aligned.m16n8k16.row.col.f32.f16.f16.f32 "
        "{%0,%1,%2,%3}, {%4,%5,%6,%7}, {%8,%9}, {%0,%1,%2,%3};"
        : "+f"(c0), "+f"(c1), "+f"(c2), "+f"(c3)
        : "r"(a0), "r"(a1), "r"(a2), "r"(a3), "r"(b0), "r"(b1));
}

__global__ __launch_bounds__(THREADS, 2) void CIN_52553219834054_kernel(
    const float* __restrict__ x,
    const float* __restrict__ b1v, const float* __restrict__ b2v,
    const float* __restrict__ Wfc, const float* __restrict__ bfcp,
    float* __restrict__ out)
{
    __shared__ __half X0p[8192];        // [i64][wq4][g8][k8_4]   (16 KB)
    __shared__ __half Hs[128 * HS_ST];  // [p128][f64 (+pad)]     (18 KB)
    __shared__ float  sb[128];          // b1 | b2
    __shared__ float  swf[128];         // Wfc
    __shared__ float  red[2];

    const int tid  = threadIdx.x;
    const int lane = tid & 31;
    const int wid  = tid >> 5;
    const int g    = lane >> 2;
    const int t    = lane & 3;
    const int wq   = wid >> 1;          // m-quarter: rows wq*32 .. wq*32+31
    const int nh   = wid & 1;           // n-half
    const int b0g  = blockIdx.x * 2;

    // stage x -> X0p (packed x0 scalars) and Hs (h0 = x)
    for (int q = tid; q < 2048; q += THREADS) {
        int bl = q >> 10, f = (q >> 4) & 63, d4 = q & 15;
        float4 v = *(const float4*)(x + (size_t)(b0g + bl) * 4096 + f * 64 + d4 * 4);
        float vv[4] = { v.x, v.y, v.z, v.w };
        #pragma unroll
        for (int e = 0; e < 4; e++) {
            int d = d4 * 4 + e;
            __half hv = __float2half(vv[e]);
            Hs[(bl * 64 + d) * HS_ST + f] = hv;
            int wqs = bl * 2 + (d >> 5);
            int dq  = d & 31;
            X0p[((f * 4 + wqs) * 8 + (dq & 7)) * 4 + (dq >> 3)] = hv;
        }
    }
    if (tid < 64)  { sb[tid] = b1v[tid]; sb[64 + tid] = b2v[tid]; }
    if (tid < 128) swf[tid] = Wfc[tid];
    if (tid < 2)   red[tid] = 0.0f;
    __syncthreads();

    // per-warp B stream base: uint4 index = gc*512 + nh*256 + j8*32 + lane
    const uint4* Wp = (const uint4*)g_Wf + (unsigned)nh * 256u + (unsigned)lane;

    uint4 buf[8];
    #pragma unroll
    for (int j8 = 0; j8 < 8; j8++) buf[j8] = Wp[(unsigned)j8 * 32u];   // chunk 0

    float pool = 0.0f;
    float acc[2][4][4];

    for (int L = 0; L < 2; L++) {
        // hoist h fragments: hfr[k8][ks][kh], row = wq*32 + k8*8 + g
        unsigned hfr[4][4][2];
        #pragma unroll
        for (int k8 = 0; k8 < 4; k8++) {
            int r = wq * 32 + k8 * 8 + g;
            #pragma unroll
            for (int ks = 0; ks < 4; ks++) {
                hfr[k8][ks][0] = *(const unsigned*)(Hs + r * HS_ST + ks * 16 + 2 * t);
                hfr[k8][ks][1] = *(const unsigned*)(Hs + r * HS_ST + ks * 16 + 2 * t + 8);
            }
        }

        #pragma unroll
        for (int s = 0; s < 2; s++)
            #pragma unroll
            for (int nt = 0; nt < 4; nt++)
                #pragma unroll
                for (int k = 0; k < 4; k++) acc[s][nt][k] = 0.0f;

        #pragma unroll 1
        for (int i = 0; i < 64; i++) {
            const int gc = L * 64 + i;
            const unsigned nx = (unsigned)((gc + 1) & 127) * 512u;   // next chunk (wraps harmlessly)

            // x0 scalars (4 k8 rows) for this quarter/chunk
            uint2 xv = *(const uint2*)(X0p + ((i * 4 + wq) * 8 + g) * 4);
            const __half* xh = (const __half*)&xv;
            __half2 xd[4];
            #pragma unroll
            for (int k8 = 0; k8 < 4; k8++) xd[k8] = __half2half2(xh[k8]);

            #pragma unroll
            for (int ks = 0; ks < 4; ks++) {
                uint4 q0 = buf[ks * 2], q1 = buf[ks * 2 + 1];
                // refill this ks-slot with next chunk's data (consumed one full chunk later)
                buf[ks * 2]     = Wp[nx + (unsigned)(ks * 2) * 32u];
                buf[ks * 2 + 1] = Wp[nx + (unsigned)(ks * 2 + 1) * 32u];
                #pragma unroll
                for (int s = 0; s < 2; s++) {
                    __half2 a0h = __hmul2(xd[2 * s],     *(__half2*)&hfr[2 * s][ks][0]);
                    __half2 a1h = __hmul2(xd[2 * s + 1], *(__half2*)&hfr[2 * s + 1][ks][0]);
                    __half2 a2h = __hmul2(xd[2 * s],     *(__half2*)&hfr[2 * s][ks][1]);
                    __half2 a3h = __hmul2(xd[2 * s + 1], *(__half2*)&hfr[2 * s + 1][ks][1]);
                    unsigned a0 = *(unsigned*)&a0h, a1 = *(unsigned*)&a1h;
                    unsigned a2 = *(unsigned*)&a2h, a3 = *(unsigned*)&a3h;
                    mma16(acc[s][0][0], acc[s][0][1], acc[s][0][2], acc[s][0][3], a0, a1, a2, a3, q0.x, q0.y);
                    mma16(acc[s][1][0], acc[s][1][1], acc[s][1][2], acc[s][1][3], a0, a1, a2, a3, q0.z, q0.w);
                    mma16(acc[s][2][0], acc[s][2][1], acc[s][2][2], acc[s][2][3], a0, a1, a2, a3, q1.x, q1.y);
                    mma16(acc[s][3][0], acc[s][3][1], acc[s][3][2], acc[s][3][3], a0, a1, a2, a3, q1.z, q1.w);
                }
            }
        }

        __syncthreads();   // all warps done reading Hs before it is overwritten

        // epilogue: bias + relu, pooled FC, Hs writeback for layer 2
        const float* bias = sb + L * 64;
        const float* wf   = swf + L * 64;
        #pragma unroll
        for (int s = 0; s < 2; s++) {
            int r0 = wq * 32 + s * 16 + g;
            int r1 = r0 + 8;
            #pragma unroll
            for (int nt = 0; nt < 4; nt++) {
                int n0 = nh * 32 + nt * 8 + 2 * t;
                int n1 = n0 + 1;
                float h00 = fmaxf(acc[s][nt][0] + bias[n0], 0.0f);
                float h01 = fmaxf(acc[s][nt][1] + bias[n1], 0.0f);
                float h10 = fmaxf(acc[s][nt][2] + bias[n0], 0.0f);
                float h11 = fmaxf(acc[s][nt][3] + bias[n1], 0.0f);
                pool += (h00 + h10) * wf[n0] + (h01 + h11) * wf[n1];
                if (L == 0) {
                    Hs[r0 * HS_ST + n0] = __float2half(h00);
                    Hs[r0 * HS_ST + n1] = __float2half(h01);
                    Hs[r1 * HS_ST + n0] = __float2half(h10);
                    Hs[r1 * HS_ST + n1] = __float2half(h11);
                }
            }
        }
        __syncthreads();   // publish Hs before next layer's fragment hoist
    }

    // pooled reduction: quarters 0,1 -> batch 0; quarters 2,3 -> batch 1
    #pragma unroll
    for (int o = 16; o; o >>= 1) pool += __shfl_xor_sync(0xFFFFFFFFu, pool, o);
    if (lane == 0) atomicAdd(&red[wq >> 1], pool);
    __syncthreads();
    if (tid < 2) out[b0g + tid] = red[tid] + bfcp[0];
}

extern "C" void kernel_launch(void* const* d_in, const int* in_sizes, int n_in,
                              void* d_out, int out_size) {
    (void)in_sizes; (void)n_in; (void)out_size;
    const float* x   = (const float*)d_in[0];
    const float* W1  = (const float*)d_in[1];
    const float* b1v = (const float*)d_in[2];
    const float* W2  = (const float*)d_in[3];
    const float* b2v = (const float*)d_in[4];
    const float* Wfc = (const float*)d_in[5];
    const float* bfc = (const float*)d_in[6];
    float* out = (float*)d_out;

    prep_kernel<<<2048, 256>>>(W1, W2);
    CIN_52553219834054_kernel<<<512, THREADS>>>(x, b1v, b2v, Wfc, bfc, out);
}